// round 12
// baseline (speedup 1.0000x reference)
#include <cuda_runtime.h>
#include <math.h>

#define NV 4096
#define EV 131072
#define EPS 1e-6f
#define EPSN 4.096e-3f   // EPS * NV
#define GB 148
#define NT 1024
#define GT (GB*NT)
#define GW (GB*32)

// ---------------- static device scratch ----------------
static __device__ float g_h1[NV*128];   // [gcn1 h | ptd1 y]
static __device__ float g_x1[NV*64];
static __device__ float g_h2[NV*48];    // [gcn2 h | ptd2 y]
static __device__ float g_Wc1[512*128];
static __device__ float g_Wc2[64*48];
static __device__ float g_deg[2*NV], g_r[2*NV];
static __device__ int   g_cntd[NV], g_cnts[NV];
static __device__ int   g_startd[NV+1], g_starts[NV+1];
static __device__ int   g_curd[NV], g_curs[NV];
static __device__ int   g_adj_d_src[EV], g_adj_d_eid[EV];
static __device__ int   g_adj_s_dst[EV], g_adj_s_eid[EV];
static __device__ float g_Y[2][NV*6], g_Qb[2][NV*6], g_Zb[2][NV*6], g_V[2][NV*6];
static __device__ float g_cs[2][6], g_U6[2][36];
static __device__ float g_UU[2][NV], g_TT[2][NV], g_ZZ[2][NV];
static __device__ float g_c[NV], g_D[3][NV], g_vi[2][NV];
static __device__ float g_smv[2][2];
static __device__ float g_nuc[2];
static __device__ double g_ds[8];
static __device__ unsigned g_barcnt = 0;
static __device__ volatile unsigned g_gen = 0;

__device__ __forceinline__ float wsum(float v){
    #pragma unroll
    for (int o = 16; o; o >>= 1) v += __shfl_xor_sync(0xffffffffu, v, o);
    return v;
}

// grid-wide barrier; all GB blocks co-resident (1 block/SM)
__device__ __forceinline__ void gridbar(){
    __syncthreads();
    if (threadIdx.x == 0){
        __threadfence();
        unsigned gen = g_gen;
        if (atomicAdd(&g_barcnt, 1) == GB-1){
            g_barcnt = 0;
            __threadfence();
            g_gen = gen + 1;
        } else {
            while (g_gen == gen) __nanosleep(32);
            __threadfence();
        }
    }
    __syncthreads();
}

// block reduce n<=16 values (blockDim = 1024); broadcast to all threads
__device__ void bred(float* vals, int n, float* sb){
    int w = threadIdx.x >> 5, l = threadIdx.x & 31;
    __syncthreads();
    for (int q = 0; q < n; q++){ float v = wsum(vals[q]); if (l == 0) sb[q*32 + w] = v; }
    __syncthreads();
    if (w == 0) for (int q = 0; q < n; q++){ float v = wsum(sb[q*32 + l]); if (l == 0) sb[q*32] = v; }
    __syncthreads();
    for (int q = 0; q < n; q++) vals[q] = sb[q*32];
}

// ---------------- device phase helpers (blocks 0/1, 1024 threads) ----------------
__device__ void dev_qr(int v, int qs, float* sb){
    float* Q = qs ? g_Zb[v] : g_Qb[v];
    int tid = threadIdx.x;
    float vv[4][6];
    #pragma unroll
    for (int rr = 0; rr < 4; rr++){ int i = tid + rr*1024;
        #pragma unroll
        for (int j = 0; j < 6; j++) vv[rr][j] = g_Y[v][i*6+j]; }
    for (int j = 0; j < 6; j++){
        for (int pass = 0; pass < 2 && j > 0; pass++){
            float h[5];
            for (int q = 0; q < j; q++){
                float s = 0;
                #pragma unroll
                for (int rr = 0; rr < 4; rr++) s += vv[rr][q]*vv[rr][j];
                h[q] = s;
            }
            bred(h, j, sb);
            for (int q = 0; q < j; q++)
                #pragma unroll
                for (int rr = 0; rr < 4; rr++) vv[rr][j] -= h[q]*vv[rr][q];
        }
        float n2 = 0;
        #pragma unroll
        for (int rr = 0; rr < 4; rr++) n2 += vv[rr][j]*vv[rr][j];
        bred(&n2, 1, sb);
        float sc = 1.f/sqrtf(fmaxf(n2, 1e-30f));
        #pragma unroll
        for (int rr = 0; rr < 4; rr++) vv[rr][j] *= sc;
    }
    float p[6] = {0,0,0,0,0,0};
    #pragma unroll
    for (int rr = 0; rr < 4; rr++){ int i = tid + rr*1024;
        #pragma unroll
        for (int j = 0; j < 6; j++){ Q[i*6+j] = vv[rr][j]; p[j] += vv[rr][j]; } }
    bred(p, 6, sb);
    if (tid < 6) g_cs[v][tid] = p[tid];
}

__device__ void dev_finB(int v, float* sb){
    int tid = threadIdx.x;
    float g[4][6];
    #pragma unroll
    for (int rr = 0; rr < 4; rr++){ int i = tid + rr*1024;
        #pragma unroll
        for (int j = 0; j < 6; j++) g[rr][j] = g_Y[v][i*6+j]; }
    float p[21]; int id = 0;
    for (int a = 0; a < 6; a++)
        for (int b = a; b < 6; b++){
            float s = 0;
            #pragma unroll
            for (int rr = 0; rr < 4; rr++) s += g[rr][a]*g[rr][b];
            p[id++] = s;
        }
    bred(p, 6, sb); bred(p+6, 6, sb); bred(p+12, 6, sb); bred(p+18, 3, sb);
    if (tid == 0){
        double A[6][6], Vv[6][6]; id = 0;
        for (int a = 0; a < 6; a++) for (int b = a; b < 6; b++){ A[a][b] = p[id]; A[b][a] = p[id]; id++; }
        for (int a = 0; a < 6; a++) for (int b = 0; b < 6; b++) Vv[a][b] = (a==b) ? 1.0 : 0.0;
        for (int sw = 0; sw < 30; sw++)
            for (int pp = 0; pp < 5; pp++) for (int q = pp+1; q < 6; q++){
                double apq = A[pp][q]; if (fabs(apq) < 1e-30) continue;
                double tau = (A[q][q]-A[pp][pp])/(2.0*apq);
                double t = (tau >= 0 ? 1.0 : -1.0)/(fabs(tau)+sqrt(1.0+tau*tau));
                double c = 1.0/sqrt(1.0+t*t), s = t*c;
                for (int i = 0; i < 6; i++){ double a1=A[i][pp],a2=A[i][q]; A[i][pp]=c*a1-s*a2; A[i][q]=s*a1+c*a2; }
                for (int i = 0; i < 6; i++){ double a1=A[pp][i],a2=A[q][i]; A[pp][i]=c*a1-s*a2; A[q][i]=s*a1+c*a2; }
                for (int i = 0; i < 6; i++){ double a1=Vv[i][pp],a2=Vv[i][q]; Vv[i][pp]=c*a1-s*a2; Vv[i][q]=s*a1+c*a2; }
            }
        int ord[6] = {0,1,2,3,4,5};
        for (int a = 0; a < 6; a++) for (int b = a+1; b < 6; b++)
            if (A[ord[b]][ord[b]] > A[ord[a]][ord[a]]){ int t2 = ord[a]; ord[a] = ord[b]; ord[b] = t2; }
        for (int kk = 0; kk < 6; kk++) for (int j = 0; j < 6; j++) g_U6[v][j*6+kk] = (float)Vv[j][ord[kk]];
    }
}

__device__ void dev_compVprep(int v, float* sb){
    int tid = threadIdx.x;
    const float* rr_ = g_r + v*NV;
    float s2[2] = {0,0};
    #pragma unroll
    for (int rr = 0; rr < 4; rr++){
        int i = tid + rr*1024;
        float gr[6];
        #pragma unroll
        for (int j = 0; j < 6; j++) gr[j] = g_Y[v][i*6+j];
        #pragma unroll
        for (int kk = 0; kk < 6; kk++){
            float s = 0;
            #pragma unroll
            for (int j = 0; j < 6; j++) s += gr[j]*g_U6[v][j*6+kk];
            g_V[v][i*6+kk] = s;
        }
        float u = g_V[v][i*6+0];
        g_UU[v][i] = u;
        if (v == 0) g_c[i] = 1.f;
        s2[0] += u; s2[1] += rr_[i]*u;
    }
    bred(s2, 2, sb);
    if (tid == 0){ g_smv[v][0] = s2[0]; g_smv[v][1] = s2[1]; }
}

__device__ void dev_mid(int v, int nd, float* sb){
    int tid = threadIdx.x;
    const float* rr_ = g_r + v*NV;
    float s0 = g_smv[v][0], s1v = g_smv[v][1];
    float pv[4]; float n2 = 0;
    #pragma unroll
    for (int rr = 0; rr < 4; rr++){
        int i = tid + rr*1024;
        float z = g_ZZ[v][i] + EPS*(s0*rr_[i] + s1v + EPSN*s0);
        if (v == 0) z *= g_c[i];
        pv[rr] = z; n2 += z*z;
    }
    bred(&n2, 1, sb);
    float inv = 1.f/sqrtf(fmaxf(n2, 1e-30f));
    #pragma unroll
    for (int rr = 0; rr < 4; rr++){ pv[rr] *= inv; g_vi[v][tid + rr*1024] = pv[rr]; }
    float u[4];
    if (v == 0){
        #pragma unroll
        for (int rr = 0; rr < 4; rr++) u[rr] = pv[rr]*g_c[tid + rr*1024];
    } else {
        #pragma unroll
        for (int rr = 0; rr < 4; rr++) u[rr] = pv[rr];
        for (int j = nd-1; j >= 0; j--){
            float dd = 0;
            #pragma unroll
            for (int rr = 0; rr < 4; rr++) dd += g_D[j][tid+rr*1024]*u[rr];
            bred(&dd, 1, sb);
            #pragma unroll
            for (int rr = 0; rr < 4; rr++) u[rr] -= dd*g_D[j][tid+rr*1024];
        }
    }
    float s2[2] = {0,0};
    #pragma unroll
    for (int rr = 0; rr < 4; rr++){
        int i = tid + rr*1024;
        g_UU[v][i] = u[rr];
        s2[0] += u[rr]; s2[1] += rr_[i]*u[rr];
    }
    bred(s2, 2, sb);
    if (tid == 0){ g_smv[v][0] = s2[0]; g_smv[v][1] = s2[1]; }
}

__device__ void dev_finprep(int v, int k, int knext, int ndp, float* sb){
    int tid = threadIdx.x;
    const float* rr_ = g_r + v*NV;
    float s0 = g_smv[v][0], s1v = g_smv[v][1];
    float s2[2] = {0,0};
    #pragma unroll
    for (int rr = 0; rr < 4; rr++){
        int i = tid + rr*1024;
        float z = g_ZZ[v][i] + EPS*(s0*rr_[i] + s1v + EPSN*s0);
        float vi = g_vi[v][i];
        float lhs = (v == 0) ? g_UU[v][i] : vi;
        s2[0] += lhs*z; s2[1] += vi*vi;
    }
    bred(s2, 2, sb);
    if (tid == 0) g_nuc[v] += sqrtf(fabsf(s2[0]/s2[1]));
    if (k >= 2 && k <= 4){
        if (v == 0){
            #pragma unroll
            for (int rr = 0; rr < 4; rr++){ int i = tid + rr*1024; g_c[i] *= g_vi[0][i]; }
        } else {
            #pragma unroll
            for (int rr = 0; rr < 4; rr++){ int i = tid + rr*1024; g_D[k-2][i] = g_vi[1][i]; }
        }
        __syncthreads();
    }
    if (knext < 0) return;
    float u[4];
    if (v == 0){
        #pragma unroll
        for (int rr = 0; rr < 4; rr++){ int i = tid + rr*1024; u[rr] = g_c[i]*g_V[0][i*6 + knext]; }
    } else {
        #pragma unroll
        for (int rr = 0; rr < 4; rr++) u[rr] = g_V[1][(tid+rr*1024)*6 + knext];
        for (int j = ndp-1; j >= 0; j--){
            float dd = 0;
            #pragma unroll
            for (int rr = 0; rr < 4; rr++) dd += g_D[j][tid+rr*1024]*u[rr];
            bred(&dd, 1, sb);
            #pragma unroll
            for (int rr = 0; rr < 4; rr++) u[rr] -= dd*g_D[j][tid+rr*1024];
        }
    }
    float s2b[2] = {0,0};
    #pragma unroll
    for (int rr = 0; rr < 4; rr++){
        int i = tid + rr*1024;
        g_UU[v][i] = u[rr];
        s2b[0] += u[rr]; s2b[1] += rr_[i]*u[rr];
    }
    bred(s2b, 2, sb);
    if (tid == 0){ g_smv[v][0] = s2b[0]; g_smv[v][1] = s2b[1]; }
}

// whole-grid sparse products
__device__ void dev_g6(int ms, int tr, const float* om1, const float* om2,
                       const float* w1, const float* w2, int gw, int lane){
    for (int idx = gw; idx < 2*NV; idx += GW){
        int v = idx >> 12, n = idx & (NV-1);
        const float* M = (ms == 0) ? g_Qb[v] : (ms == 1) ? g_Zb[v] : (v ? om2 : om1);
        const float* w = v ? w2 : w1;
        const int* st    = tr ? g_startd    : g_starts;
        const int* other = tr ? g_adj_d_src : g_adj_s_dst;
        const int* eid   = tr ? g_adj_d_eid : g_adj_s_eid;
        float acc[6] = {0,0,0,0,0,0};
        int p1e = st[n+1];
        for (int p = st[n] + lane; p < p1e; p += 32){
            float we = w[eid[p]];
            const float* mr = M + (size_t)other[p]*6;
            #pragma unroll
            for (int j = 0; j < 6; j++) acc[j] += we*mr[j];
        }
        #pragma unroll
        for (int j = 0; j < 6; j++) acc[j] = wsum(acc[j]);
        if (lane == 0)
            #pragma unroll
            for (int j = 0; j < 6; j++) g_Y[v][n*6+j] = acc[j] + EPS*g_cs[v][j];
    }
}

__device__ void dev_gT(const float* w1, const float* w2, int gw, int lane){
    for (int idx = gw; idx < 2*NV; idx += GW){
        int v = idx >> 12, n = idx & (NV-1);
        const float* w = v ? w2 : w1;
        float acc = 0;
        int p1e = g_startd[n+1];
        for (int p = g_startd[n] + lane; p < p1e; p += 32)
            acc += w[g_adj_d_eid[p]]*g_UU[v][g_adj_d_src[p]];
        acc = wsum(acc);
        if (lane == 0) g_TT[v][n] = acc;
    }
}

__device__ void dev_gZ(const float* w1, const float* w2, int gw, int lane){
    for (int idx = gw; idx < 2*NV; idx += GW){
        int v = idx >> 12, n = idx & (NV-1);
        const float* w = v ? w2 : w1;
        float acc = 0;
        int p1e = g_starts[n+1];
        for (int p = g_starts[n] + lane; p < p1e; p += 32)
            acc += w[g_adj_s_eid[p]]*g_TT[v][g_adj_s_dst[p]];
        acc = wsum(acc);
        if (lane == 0) g_ZZ[v][n] = acc;
    }
}

// ---------------- the mega kernel ----------------
__global__ void __launch_bounds__(1024, 1) mega(
    const float* __restrict__ x, const int* __restrict__ src, const int* __restrict__ dst,
    const float* __restrict__ g1w, const float* __restrict__ g1b,
    const float* __restrict__ g2w, const float* __restrict__ g2b,
    const float* __restrict__ p1w1, const float* __restrict__ p1b1,
    const float* __restrict__ p1w2, const float* __restrict__ p1b2,
    const float* __restrict__ p2w1, const float* __restrict__ p2b1,
    const float* __restrict__ p2w2, const float* __restrict__ p2b2,
    const float* __restrict__ om1, const float* __restrict__ om2,
    float* __restrict__ lsm, float* __restrict__ smx, float* __restrict__ loss,
    float* __restrict__ e_s1, float* __restrict__ e_s2, float* __restrict__ calib)
{
    __shared__ union {
        float red[512];
        int wt[32];
        struct { float As[64][33]; float Bs[64][132]; } t1;
        struct { float As[64][65]; float Bs[64][49];  } t2;
    } sh;
    const int B = blockIdx.x, T = threadIdx.x;
    const int gt = B*NT + T;
    const int lane = T & 31;
    const int gw = B*32 + (T >> 5);

    // ---- P0: zero state + weight concat ----
    for (int i = gt; i < 2*NV; i += GT){ g_deg[i] = 1.f; g_r[i] = 0.f; }
    for (int i = gt; i < NV; i += GT){ g_cntd[i] = 0; g_cnts[i] = 0; }
    if (gt < 8) g_ds[gt] = 0.0;
    if (gt < 2) g_nuc[gt] = 0.f;
    for (int i = gt; i < 512*128; i += GT){
        int row = i >> 7, col = i & 127;
        g_Wc1[i] = (col < 64) ? g1w[row*64+col] : p1w1[row*64 + (col-64)];
    }
    for (int i = gt; i < 64*48; i += GT){
        int row = i/48, col = i - row*48;
        g_Wc2[i] = (col < 16) ? g2w[row*16+col] : p2w1[row*32 + (col-16)];
    }
    gridbar();

    // ---- P1: degree hist + GEMM1 (x @ Wc1 -> h1) ----
    for (int e = gt; e < EV; e += GT){ atomicAdd(&g_cntd[dst[e]], 1); atomicAdd(&g_cnts[src[e]], 1); }
    if (B < 128){
        int m0 = B*32;
        int col = T & 127, rq = T >> 7;
        float acc[4] = {0,0,0,0};
        for (int k0 = 0; k0 < 512; k0 += 64){
            for (int i = T; i < 32*64; i += NT){
                int row = i >> 6, kk = i & 63;
                sh.t1.As[kk][row] = x[(size_t)(m0+row)*512 + k0 + kk];
            }
            for (int i = T; i < 64*128; i += NT){
                int kk = i >> 7, n = i & 127;
                sh.t1.Bs[kk][n] = g_Wc1[(k0+kk)*128 + n];
            }
            __syncthreads();
            #pragma unroll 16
            for (int kk = 0; kk < 64; kk++){
                float b = sh.t1.Bs[kk][col];
                #pragma unroll
                for (int r = 0; r < 4; r++) acc[r] += sh.t1.As[kk][rq*4+r]*b;
            }
            __syncthreads();
        }
        #pragma unroll
        for (int r = 0; r < 4; r++)
            g_h1[(size_t)(m0+rq*4+r)*128 + col] = acc[r];
    }
    gridbar();

    // ---- P2: scan (block 0) + gate1 (all) ----
    if (B == 0){
        int t = T, l = t & 31, w = t >> 5;
        for (int a = 0; a < 2; a++){
            const int* cnt = a ? g_cnts : g_cntd;
            int* start = a ? g_starts : g_startd;
            int* cur   = a ? g_curs  : g_curd;
            int c[4]; int s = 0;
            #pragma unroll
            for (int q = 0; q < 4; q++){ c[q] = cnt[t*4+q]; s += c[q]; }
            int v = s;
            #pragma unroll
            for (int o = 1; o < 32; o <<= 1){ int n = __shfl_up_sync(~0u, v, o); if (l >= o) v += n; }
            if (l == 31) sh.wt[w] = v;
            __syncthreads();
            if (w == 0){
                int xx = sh.wt[l];
                #pragma unroll
                for (int o = 1; o < 32; o <<= 1){ int n = __shfl_up_sync(~0u, xx, o); if (l >= o) xx += n; }
                sh.wt[l] = xx;
            }
            __syncthreads();
            int run = v - s + (w ? sh.wt[w-1] : 0);
            #pragma unroll
            for (int q = 0; q < 4; q++){ start[t*4+q] = run; cur[t*4+q] = run; run += c[q]; }
            if (t == 1023) start[NV] = run;
            __syncthreads();
        }
    }
    {
        double a0acc = 0, a1acc = 0;
        for (int e = gw; e < EV; e += GW){
            int s = src[e], d = dst[e];
            const float* ys = g_h1 + (size_t)s*128 + 64;
            const float* yd = g_h1 + (size_t)d*128 + 64;
            float a = fmaxf(ys[lane]    - yd[lane]    + p1b1[lane],    0.f)*p1w2[lane]
                    + fmaxf(ys[lane+32] - yd[lane+32] + p1b1[lane+32], 0.f)*p1w2[lane+32];
            a = wsum(a);
            if (lane == 0){
                a += p1b2[0]; a = a*a;
                float sv = 1.f/(1.f+expf(-a));
                sv = fminf(fmaxf(sv, 0.f), 1.f);
                e_s1[e] = sv;
                atomicAdd(&g_deg[d], sv);
                atomicAdd(&g_r[s], sv);
                a0acc += sv; a1acc += (double)sv*(double)sv;
            }
        }
        if (lane == 0){ atomicAdd(&g_ds[0], a0acc); atomicAdd(&g_ds[1], a1acc); }
    }
    gridbar();

    // ---- P3: CSR fill + omega colsums (blocks 0,1) ----
    for (int e = gt; e < EV; e += GT){
        int s = src[e], d = dst[e];
        int pd = atomicAdd(&g_curd[d], 1); g_adj_d_src[pd] = s; g_adj_d_eid[pd] = e;
        int ps = atomicAdd(&g_curs[s], 1); g_adj_s_dst[ps] = d; g_adj_s_eid[ps] = e;
    }
    if (B < 2){
        const float* M = B ? om2 : om1;
        float p[6] = {0,0,0,0,0,0};
        #pragma unroll
        for (int rr = 0; rr < 4; rr++){
            int i = T + rr*1024;
            #pragma unroll
            for (int j = 0; j < 6; j++) p[j] += M[i*6+j];
        }
        bred(p, 6, sh.red);
        if (T < 6) g_cs[B][T] = p[T];
    }
    gridbar();

    // ---- P4: GCN conv 1 (gather) + relu ----
    for (int d = gw; d < NV; d += GW){
        float degd = g_deg[d], did = rsqrtf(degd);
        float a0 = (1.f/degd)*g_h1[(size_t)d*128 + lane];
        float a1 = (1.f/degd)*g_h1[(size_t)d*128 + lane + 32];
        int p1e = g_startd[d+1];
        for (int p = g_startd[d]; p < p1e; p++){
            int s = g_adj_d_src[p]; int e = g_adj_d_eid[p];
            float cf = rsqrtf(g_deg[s])*e_s1[e]*did;
            a0 += cf*g_h1[(size_t)s*128 + lane];
            a1 += cf*g_h1[(size_t)s*128 + lane + 32];
        }
        g_x1[(size_t)d*64 + lane]      = fmaxf(a0 + g1b[lane],      0.f);
        g_x1[(size_t)d*64 + lane + 32] = fmaxf(a1 + g1b[lane + 32], 0.f);
    }
    gridbar();

    // ---- P5: GEMM2 (x1 @ Wc2 -> h2) ----
    if (B < 64){
        int m0 = B*64;
        for (int i = T; i < 64*64; i += NT){
            int row = i >> 6, kk = i & 63;
            sh.t2.As[kk][row] = g_x1[(size_t)(m0+row)*64 + kk];
        }
        for (int i = T; i < 64*48; i += NT){
            int kk = i/48, n = i - kk*48;
            sh.t2.Bs[kk][n] = g_Wc2[kk*48 + n];
        }
        __syncthreads();
        for (int o = T; o < 64*48; o += NT){
            int row = o/48, n = o - row*48;
            float acc = 0;
            #pragma unroll 16
            for (int kk = 0; kk < 64; kk++) acc += sh.t2.As[kk][row]*sh.t2.Bs[kk][n];
            g_h2[(size_t)(m0+row)*48 + n] = acc;
        }
        __syncthreads();
    }
    gridbar();

    // ---- P6: gate2 ----
    {
        double b0acc = 0, b1acc = 0;
        for (int e = gw; e < EV; e += GW){
            int s = src[e], d = dst[e];
            const float* ys = g_h2 + (size_t)s*48 + 16;
            const float* yd = g_h2 + (size_t)d*48 + 16;
            float a = fmaxf(ys[lane] - yd[lane] + p2b1[lane], 0.f)*p2w2[lane];
            a = wsum(a);
            if (lane == 0){
                a += p2b2[0]; a = a*a;
                float sv = 1.f/(1.f+expf(-a));
                sv = fminf(fmaxf(sv, 0.f), 1.f);
                e_s2[e] = sv;
                atomicAdd(&g_deg[NV+d], sv);
                atomicAdd(&g_r[NV+s], sv);
                b0acc += sv; b1acc += (double)sv*(double)sv;
            }
        }
        if (lane == 0){ atomicAdd(&g_ds[2], b0acc); atomicAdd(&g_ds[3], b1acc); }
    }
    gridbar();

    // ---- P7: GCN conv 2 + softmax/log_softmax + calib (fused per warp) ----
    {
        double cacc = 0;
        for (int n = gw; n < NV; n += GW){
            float vcol = -1e30f;
            float degd = g_deg[NV+n];
            if (lane < 16){
                float did = rsqrtf(degd);
                float a0 = (1.f/degd)*g_h2[(size_t)n*48 + lane];
                int p1e = g_startd[n+1];
                for (int p = g_startd[n]; p < p1e; p++){
                    int s = g_adj_d_src[p]; int e = g_adj_d_eid[p];
                    float cf = rsqrtf(g_deg[NV+s])*e_s2[e]*did;
                    a0 += cf*g_h2[(size_t)s*48 + lane];
                }
                vcol = a0 + g2b[lane];
            }
            float m1 = vcol;
            #pragma unroll
            for (int o = 16; o; o >>= 1) m1 = fmaxf(m1, __shfl_xor_sync(~0u, m1, o));
            unsigned bal = __ballot_sync(~0u, vcol == m1);
            int leader = __ffs(bal) - 1;
            float v2 = (lane == leader) ? -1e30f : vcol;
            float m2 = v2;
            #pragma unroll
            for (int o = 16; o; o >>= 1) m2 = fmaxf(m2, __shfl_xor_sync(~0u, m2, o));
            float ev = (lane < 16) ? expf(vcol - m1) : 0.f;
            float se = wsum(ev);
            if (lane < 16){
                lsm[n*16 + lane] = vcol - m1 - logf(se);
                smx[n*16 + lane] = ev/se;
            }
            if (lane == 0) cacc += (double)(m2 - m1);
        }
        if (lane == 0) atomicAdd(&g_ds[6], cacc);
    }
    gridbar();

    // ---- SVD: randomized range finder (niter = 2), both variants ----
    dev_g6(2, 0, om1, om2, e_s1, e_s2, gw, lane); gridbar();
    if (B < 2) dev_qr(B, 0, sh.red);
    gridbar();
    for (int it = 0; it < 2; it++){
        dev_g6(0, 1, om1, om2, e_s1, e_s2, gw, lane); gridbar();
        if (B < 2) dev_qr(B, 1, sh.red);
        gridbar();
        dev_g6(1, 0, om1, om2, e_s1, e_s2, gw, lane); gridbar();
        if (B < 2) dev_qr(B, 0, sh.red);
        gridbar();
    }
    dev_g6(0, 1, om1, om2, e_s1, e_s2, gw, lane); gridbar();
    if (B < 2){
        dev_finB(B, sh.red);
        __syncthreads();
        dev_compVprep(B, sh.red);
    }
    gridbar();

    // ---- nuclear loss: 6 deflation steps ----
    for (int k = 0; k < 6; k++){
        int nd = k - 2; if (nd < 0) nd = 0; if (nd > 3) nd = 3;
        dev_gT(e_s1, e_s2, gw, lane); gridbar();
        dev_gZ(e_s1, e_s2, gw, lane); gridbar();
        if (B < 2) dev_mid(B, nd, sh.red);
        gridbar();
        dev_gT(e_s1, e_s2, gw, lane); gridbar();
        dev_gZ(e_s1, e_s2, gw, lane); gridbar();
        int knext = (k < 5) ? k+1 : -1;
        int ndp = 0;
        if (knext >= 0){ ndp = knext - 2; if (ndp < 0) ndp = 0; if (ndp > 3) ndp = 3; }
        if (B < 2) dev_finprep(B, k, knext, ndp, sh.red);
        gridbar();
    }

    // ---- finalize scalars ----
    if (B == 0 && T == 0){
        double E = (double)EV;
        double c1 = g_ds[1]/E - (g_ds[0]/E)*(g_ds[0]/E);
        double c2 = g_ds[3]/E - (g_ds[2]/E)*(g_ds[2]/E);
        loss[0]  = (float)(0.01*(c1+c2) + 0.01*((double)g_nuc[0] + (double)g_nuc[1]));
        calib[0] = (float)(g_ds[6]/(double)NV);
    }
}

extern "C" void kernel_launch(void* const* d_in, const int* in_sizes, int n_in,
                              void* d_out, int out_size){
    const float* x     = (const float*)d_in[0];
    const int*   ei    = (const int*)d_in[1];
    const int*   src   = ei;
    const int*   dst   = ei + EV;

    float* out   = (float*)d_out;
    float* lsm   = out;
    float* smx   = out + NV*16;
    float* loss  = out + 2*NV*16;
    float* s1    = out + 2*NV*16 + 1;
    float* s2    = s1 + EV;
    float* calib = s2 + EV;

    mega<<<GB, NT>>>(
        x, src, dst,
        (const float*)d_in[2], (const float*)d_in[3],
        (const float*)d_in[4], (const float*)d_in[5],
        (const float*)d_in[6], (const float*)d_in[7],
        (const float*)d_in[8], (const float*)d_in[9],
        (const float*)d_in[10], (const float*)d_in[11],
        (const float*)d_in[12], (const float*)d_in[13],
        (const float*)d_in[14], (const float*)d_in[15],
        lsm, smx, loss, s1, s2, calib);
}